// round 13
// baseline (speedup 1.0000x reference)
#include <cuda_runtime.h>
#include <cuda_bf16.h>
#include <math.h>

#define BATCH 1024
#define NFEAT 65536
#define ZD 32
#define NG 16
#define NF 64
#define NR 32
#define KCS 16
#define KPC (NFEAT / KCS)     // 4096 K per CTA
#define NSTG (KPC / 64)       // 64 stages of BK=64

typedef unsigned int u32;

__device__ float g_zpart[KCS * BATCH * 96];
__device__ float g_s2part[KCS * BATCH];
__device__ float g_zraw[BATCH * 64];
__device__ float g_PF[BATCH * ZD];
__device__ float g_s2[BATCH];
__device__ float g_spF[NG * ZD * NF];
__device__ float g_spR1[NG * ZD * NR];
__device__ float g_spR2[NG * ZD * NR];
__device__ float g_GG[NG * ZD * ZD];
__device__ float g_perb[BATCH];
__device__ float g_varloss;
__device__ __nv_bfloat16 g_WcT[64 * NFEAT];   // [n][k] bf16 W1|W2 transposed
__device__ int g_sIdx[BATCH];
__device__ int g_gcnt[NG];
__device__ int g_goff[NG];

// dynamic smem layout (bytes)
#define SMO_A    0u           // 2 slots x 64 rows x 72 bf16  (9216 B/slot)
#define SMO_B    18432u       // 2 slots x 96 rows x 72 bf16  (13824 B/slot)
#define SMO_F    46080u       // 2048 floats
#define SMO_R1   54272u       // 1024 floats
#define SMO_R2   58368u       // 1024 floats
#define SMO_IDX  62464u       // 64 ints
#define SM_TOT   62720u

static __device__ __forceinline__ float softplusf(float x) {
    return fmaxf(x, 0.f) + log1pf(expf(-fabsf(x)));
}
static __device__ __forceinline__ u32 cvt2(float a, float b) {
    __nv_bfloat162 h = __floats2bfloat162_rn(a, b);
    return *reinterpret_cast<u32*>(&h);
}
static __device__ __forceinline__ void cpa16(u32 dst, const void* src) {
    asm volatile("cp.async.cg.shared.global [%0], [%1], 16;" :: "r"(dst), "l"(src) : "memory");
}
static __device__ __forceinline__ void sts128(u32 addr, u32 x, u32 y, u32 z, u32 w) {
    asm volatile("st.shared.v4.b32 [%0], {%1,%2,%3,%4};"
                 :: "r"(addr), "r"(x), "r"(y), "r"(z), "r"(w) : "memory");
}
static __device__ __forceinline__ void ldsm4(u32& r0, u32& r1, u32& r2, u32& r3, u32 addr) {
    asm volatile("ldmatrix.sync.aligned.m8n8.x4.shared.b16 {%0,%1,%2,%3}, [%4];"
                 : "=r"(r0), "=r"(r1), "=r"(r2), "=r"(r3) : "r"(addr));
}
static __device__ __forceinline__ void ldsm2(u32& r0, u32& r1, u32 addr) {
    asm volatile("ldmatrix.sync.aligned.m8n8.x2.shared.b16 {%0,%1}, [%2];"
                 : "=r"(r0), "=r"(r1) : "r"(addr));
}
static __device__ __forceinline__ void mma16816(float* c, u32 a0, u32 a1, u32 a2, u32 a3,
                                                u32 b0, u32 b1) {
    asm volatile(
        "mma.sync.aligned.m16n8k16.row.col.f32.bf16.bf16.f32 "
        "{%0,%1,%2,%3}, {%4,%5,%6,%7}, {%8,%9}, {%0,%1,%2,%3};"
        : "+f"(c[0]), "+f"(c[1]), "+f"(c[2]), "+f"(c[3])
        : "r"(a0), "r"(a1), "r"(a2), "r"(a3), "r"(b0), "r"(b1));
}

// ---------------- fused prologue: WcT transpose+cvt | softplus | group sort ------
__global__ void __launch_bounds__(1024) k_pre(const float* __restrict__ W1,
                                              const float* __restrict__ W2,
                                              const float* __restrict__ ff,
                                              const float* __restrict__ r1,
                                              const float* __restrict__ r2,
                                              const int* __restrict__ groups) {
    int bx = blockIdx.x, t = threadIdx.x;
    if (bx < 1024) {
        __shared__ float tile[128][33];
        int w = bx >> 9;
        int k0 = (bx & 511) * 128;
        int tx = t & 31, ty = t >> 5;          // 32 x 32
        const float* W = w ? W2 : W1;
        #pragma unroll
        for (int i = 0; i < 4; i++)
            tile[ty + 32 * i][tx] = W[(size_t)(k0 + ty + 32 * i) * 32 + tx];
        __syncthreads();
        int n = t >> 5;
        int jj = (t & 31) * 2;
        u32* dst = (u32*)(g_WcT + (size_t)(w * 32 + n) * NFEAT + k0);
        #pragma unroll
        for (int q = 0; q < 2; q++) {
            int k = (jj + q) * 2;
            dst[jj + q] = cvt2(tile[k][n], tile[k + 1][n]);
        }
    } else if (bx < 1088) {
        int i = (bx - 1024) * 1024 + t;
        const int nF = NG * ZD * NF, nR = NG * ZD * NR;
        if (i < nF) g_spF[i] = softplusf(ff[i]);
        else if (i < nF + nR) g_spR1[i - nF] = softplusf(r1[i - nF]);
        else if (i < nF + 2 * nR) g_spR2[i - nF - nR] = softplusf(r2[i - nF - nR]);
    } else {
        __shared__ int warpCnt[32][16];
        __shared__ int warpOff[32][16];
        __shared__ int goff[16], gcnt[16];
        int w = t >> 5, lane = t & 31;
        int g = groups[t];
        u32 mOwn = 0;
        #pragma unroll
        for (int gi = 0; gi < 16; gi++) {
            u32 m = __ballot_sync(0xffffffffu, g == gi);
            if (g == gi) mOwn = m;
            if (lane == gi) warpCnt[w][gi] = __popc(m);
        }
        __syncthreads();
        if (t < 16) {
            int s = 0;
            for (int w2 = 0; w2 < 32; w2++) { warpOff[w2][t] = s; s += warpCnt[w2][t]; }
            gcnt[t] = s;
        }
        __syncthreads();
        if (t == 0) {
            int s = 0;
            for (int i = 0; i < 16; i++) { goff[i] = s; s += gcnt[i]; }
        }
        __syncthreads();
        int rank = __popc(mOwn & ((1u << lane) - 1u));
        g_sIdx[goff[g] + warpOff[w][g] + rank] = t;
        if (t < 16) { g_gcnt[t] = gcnt[t]; g_goff[t] = goff[t]; }
    }
}

// ---------------- fused tensor-core GEMM: 64x96 tiles, 4 warps (2x2), 128 thr ----
// warp tile 32 rows x 48 cols. Crossbar reads/stage: 2*A + 2*B = 46 KB (was 64.5).
__global__ void __launch_bounds__(128) g_mm(const float* __restrict__ feat) {
    extern __shared__ char smc[];
    u32 sbase = (u32)__cvta_generic_to_shared(smc);
    float* sF = (float*)(smc + SMO_F);
    float* sR1 = (float*)(smc + SMO_R1);
    float* sR2 = (float*)(smc + SMO_R2);
    int* sIdx = (int*)(smc + SMO_IDX);

    int mt = blockIdx.x, kc = blockIdx.y;
    int g = mt / 3, ti = mt % 3;
    int nb = g_gcnt[g];
    int m0 = ti * 64;
    if (m0 >= nb) return;
    int p0 = g_goff[g] + m0;
    int vr = nb - m0; if (vr > 64) vr = 64;
    int t = threadIdx.x;

    for (int i = t; i < ZD * NF; i += 128) sF[i] = g_spF[g * ZD * NF + i];
    for (int i = t; i < ZD * NR; i += 128) {
        sR1[i] = g_spR1[g * ZD * NR + i];
        sR2[i] = g_spR2[g * ZD * NR + i];
    }
    if (t < 64) sIdx[t] = g_sIdx[(t < vr) ? (p0 + t) : p0];
    __syncthreads();

    int lane = t & 31, wid = t >> 5;
    int wm = wid & 1, wn = wid >> 1;          // 2 x 2, warp tile 32 x 48
    float acc[2][6][4];
    #pragma unroll
    for (int mf = 0; mf < 2; mf++)
        #pragma unroll
        for (int nf = 0; nf < 6; nf++)
            #pragma unroll
            for (int q = 0; q < 4; q++) acc[mf][nf][q] = 0.f;

    int ar = t >> 1, aq = t & 1;              // 64 rows x 2 threads (32 fp32 each)
    bool aval = ar < vr;
    const float* arow = feat + (size_t)sIdx[ar] * NFEAT + aq * 32;
    int wz = t >> 2, wi0e = (t & 3) * 16;     // WP: 32 rows x 4 threads (16 bf16 each)
    int kb0 = kc * KPC;
    float sq = 0.f;

    // B cp.async: 64 rows x 128B; 2 threads/row x 64B
    int brow = t >> 1, bch = (t & 1) * 4;
    const char* bsrc = (const char*)(g_WcT + (size_t)brow * NFEAT) + bch * 16;
    u32 bdstBase = sbase + SMO_B + (u32)brow * 144 + (u32)bch * 16;

    #define STAGE_B(s, kb)                                                        \
        do {                                                                      \
            u32 _d = bdstBase + ((u32)(s) & 1u) * 13824u;                         \
            const char* _s = bsrc + (size_t)(kb) * 2;                             \
            cpa16(_d, _s); cpa16(_d + 16, _s + 16);                               \
            cpa16(_d + 32, _s + 32); cpa16(_d + 48, _s + 48);                     \
            asm volatile("cp.async.commit_group;");                               \
        } while (0)

    #define STAGE_AWP(s, kb, rg)                                                  \
        do {                                                                      \
            u32 _ab = sbase + SMO_A + ((u32)(s) & 1u) * 9216u + (u32)ar * 144 + (u32)aq * 64; \
            if (aval) {                                                           \
                _Pragma("unroll")                                                 \
                for (int _i = 0; _i < 8; _i++)                                    \
                    sq += rg[_i].x * rg[_i].x + rg[_i].y * rg[_i].y +             \
                          rg[_i].z * rg[_i].z + rg[_i].w * rg[_i].w;              \
            }                                                                     \
            _Pragma("unroll")                                                     \
            for (int _j = 0; _j < 4; _j++)                                        \
                sts128(_ab + _j * 16,                                             \
                       cvt2(rg[2*_j].x, rg[2*_j].y), cvt2(rg[2*_j].z, rg[2*_j].w),\
                       cvt2(rg[2*_j+1].x, rg[2*_j+1].y), cvt2(rg[2*_j+1].z, rg[2*_j+1].w)); \
            int _f = (kb) >> 10, _r = (((kb) >> 5) & 31) + (wi0e >> 5);           \
            float _c0 = sF[wz * NF + _f] * sR1[wz * NR + _r];                     \
            int _s0 = wi0e & 31;                                                  \
            u32 _wb = sbase + SMO_B + ((u32)(s) & 1u) * 13824u + (u32)(64 + wz) * 144 + (u32)wi0e * 2; \
            sts128(_wb,                                                           \
                   cvt2(_c0 * sR2[wz * NR + _s0 + 0], _c0 * sR2[wz * NR + _s0 + 1]), \
                   cvt2(_c0 * sR2[wz * NR + _s0 + 2], _c0 * sR2[wz * NR + _s0 + 3]), \
                   cvt2(_c0 * sR2[wz * NR + _s0 + 4], _c0 * sR2[wz * NR + _s0 + 5]), \
                   cvt2(_c0 * sR2[wz * NR + _s0 + 6], _c0 * sR2[wz * NR + _s0 + 7])); \
            sts128(_wb + 16,                                                      \
                   cvt2(_c0 * sR2[wz * NR + _s0 + 8], _c0 * sR2[wz * NR + _s0 + 9]), \
                   cvt2(_c0 * sR2[wz * NR + _s0 + 10], _c0 * sR2[wz * NR + _s0 + 11]), \
                   cvt2(_c0 * sR2[wz * NR + _s0 + 12], _c0 * sR2[wz * NR + _s0 + 13]), \
                   cvt2(_c0 * sR2[wz * NR + _s0 + 14], _c0 * sR2[wz * NR + _s0 + 15])); \
        } while (0)

    float4 rNext[8];
    if (aval) {
        const float4* s4 = (const float4*)(arow + kb0);
        #pragma unroll
        for (int i = 0; i < 8; i++) rNext[i] = s4[i];
    }
    STAGE_B(0, kb0);

    for (int kt = 0; kt < NSTG; kt++) {
        // stage A(kt)+WP(kt) into slot kt&1 (safe: last read 2 iters ago)
        STAGE_AWP(kt, kb0 + kt * 64, rNext);
        // prefetch B(kt+1) into slot (kt+1)&1 (safe: last read in iter kt-1, synced)
        if (kt + 1 < NSTG) {
            STAGE_B(kt + 1, kb0 + (kt + 1) * 64);
        } else {
            asm volatile("cp.async.commit_group;");
        }
        // LDG A(kt+1)
        if (aval && kt + 1 < NSTG) {
            const float4* s4 = (const float4*)(arow + kb0 + (kt + 1) * 64);
            #pragma unroll
            for (int i = 0; i < 8; i++) rNext[i] = s4[i];
        }
        asm volatile("cp.async.wait_group 1;");   // B(kt) landed
        __syncthreads();
        {
            u32 aBase = sbase + SMO_A + ((u32)kt & 1u) * 9216u;
            u32 bBase = sbase + SMO_B + ((u32)kt & 1u) * 13824u;
            #pragma unroll
            for (int ks = 0; ks < 4; ks++) {
                int kbs = ks * 16;
                u32 b0[6], b1[6];
                #pragma unroll
                for (int nf = 0; nf < 6; nf++) {
                    int n = wn * 48 + nf * 8 + (lane & 7);
                    ldsm2(b0[nf], b1[nf], bBase + (u32)(n * 72 + kbs + ((lane >> 3) & 1) * 8) * 2);
                }
                #pragma unroll
                for (int mf = 0; mf < 2; mf++) {
                    int row = wm * 32 + mf * 16 + (lane & 15);
                    u32 a0, a1, a2, a3;
                    ldsm4(a0, a1, a2, a3, aBase + (u32)(row * 72 + kbs + (lane >> 4) * 8) * 2);
                    #pragma unroll
                    for (int nf = 0; nf < 6; nf++)
                        mma16816(acc[mf][nf], a0, a1, a2, a3, b0[nf], b1[nf]);
                }
            }
        }
        __syncthreads();
    }

    // s2 partials (2 threads per row)
    sq += __shfl_down_sync(0xffffffffu, sq, 1, 2);
    if (aq == 0 && aval) g_s2part[kc * BATCH + p0 + ar] = sq;

    // epilogue: scatter fp32 partials
    #pragma unroll
    for (int mf = 0; mf < 2; mf++) {
        #pragma unroll
        for (int half = 0; half < 2; half++) {
            int r = wm * 32 + mf * 16 + (lane >> 2) + half * 8;
            if (r < vr) {
                int p = p0 + r;
                float* dst = g_zpart + ((size_t)kc * BATCH + p) * 96;
                #pragma unroll
                for (int nf = 0; nf < 6; nf++) {
                    int ncol = wn * 48 + nf * 8 + (lane & 3) * 2;
                    float2 v = half ? make_float2(acc[mf][nf][2], acc[mf][nf][3])
                                    : make_float2(acc[mf][nf][0], acc[mf][nf][1]);
                    *(float2*)(dst + ncol) = v;
                }
            }
        }
    }
    #undef STAGE_B
    #undef STAGE_AWP
}

// ---------------- fused: reduce split-K partials | gram | varloss ----------------
__global__ void k_redfac() {
    int bx = blockIdx.x, t = threadIdx.x;
    if (bx < 389) {
        int i = bx * 256 + t;
        if (i < BATCH * 96) {
            int p = i / 96, n = i - p * 96;
            float s = 0.f;
            for (int kc = 0; kc < KCS; kc++) s += g_zpart[((size_t)kc * BATCH + p) * 96 + n];
            int b = g_sIdx[p];
            if (n < 64) g_zraw[b * 64 + n] = s;
            else g_PF[b * 32 + n - 64] = s;
        } else if (i < BATCH * 96 + BATCH) {
            int p = i - BATCH * 96;
            float s = 0.f;
            for (int kc = 0; kc < KCS; kc++) s += g_s2part[kc * BATCH + p];
            g_s2[g_sIdx[p]] = s;
        }
    } else if (bx < 405) {
        __shared__ float s1[ZD * NR], s2m[ZD * NR], sf[ZD * NF];
        int g = bx - 389;
        for (int i = t; i < ZD * NR; i += 256) {
            s1[i] = g_spR1[g * ZD * NR + i];
            s2m[i] = g_spR2[g * ZD * NR + i];
        }
        for (int i = t; i < ZD * NF; i += 256) sf[i] = g_spF[g * ZD * NF + i];
        __syncthreads();
        for (int q = t; q < ZD * ZD; q += 256) {
            int z = q >> 5, z2 = q & 31;
            float a = 0.f, b = 0.f, c = 0.f;
            #pragma unroll
            for (int r = 0; r < NR; r++) {
                a += s1[z * NR + r] * s1[z2 * NR + r];
                b += s2m[z * NR + r] * s2m[z2 * NR + r];
            }
            #pragma unroll
            for (int f = 0; f < NF; f++) c += sf[z * NF + f] * sf[z2 * NF + f];
            g_GG[g * ZD * ZD + q] = a * b * c;
        }
    } else {
        __shared__ float rf[256], rr[256];
        float af = 0.f, ar = 0.f;
        for (int idx = t; idx < 4096; idx += 256) {
            float s = 0.f, ss = 0.f;
            if (idx < 2048) {
                #pragma unroll
                for (int g = 0; g < 16; g++) { float x = g_spF[g * 2048 + idx]; s += x; ss += x * x; }
                af += (ss - s * s * (1.f / 16.f)) * (1.f / 15.f);
            } else if (idx < 3072) {
                int j = idx - 2048;
                #pragma unroll
                for (int g = 0; g < 16; g++) { float x = g_spR1[g * 1024 + j]; s += x; ss += x * x; }
                ar += (ss - s * s * (1.f / 16.f)) * (1.f / 15.f);
            } else {
                int j = idx - 3072;
                #pragma unroll
                for (int g = 0; g < 16; g++) { float x = g_spR2[g * 1024 + j]; s += x; ss += x * x; }
                ar += (ss - s * s * (1.f / 16.f)) * (1.f / 15.f);
            }
        }
        rf[t] = af; rr[t] = ar;
        __syncthreads();
        for (int o = 128; o > 0; o >>= 1) {
            if (t < o) { rf[t] += rf[t + o]; rr[t] += rr[t + o]; }
            __syncthreads();
        }
        if (t == 0) g_varloss = rf[0] * (1.f / 64.f) + rr[0] * (1.f / 32.f);
    }
}

// ---------------- fused VAE head + per-sample assembly ----------------
__global__ void k_head(const float* __restrict__ W1, const float* __restrict__ W2,
                       const float* __restrict__ b1, const float* __restrict__ b2,
                       const float* __restrict__ ge, const int* __restrict__ groups,
                       const float* __restrict__ noise, const float* __restrict__ linW,
                       const float* __restrict__ linb, const float* __restrict__ weights,
                       const int* __restrict__ labels, const float* __restrict__ lbias) {
    int t = threadIdx.x, b = blockIdx.x * 8 + (t >> 5), z = t & 31;
    int g = groups[b];
    float e0 = ge[g * 2], e1 = ge[g * 2 + 1];
    float mu = g_zraw[b * 64 + z] + b1[z] + e0 * W1[65536 * 32 + z] + e1 * W1[65537 * 32 + z];
    float ls = g_zraw[b * 64 + 32 + z] + b2[z] + e0 * W2[65536 * 32 + z] + e1 * W2[65537 * 32 + z];
    float sig = 1e-6f + expf(ls);
    float kt = -logf(sig) + 0.5f * (sig * sig + mu * mu - 1.f);
    #pragma unroll
    for (int o = 16; o > 0; o >>= 1) kt += __shfl_xor_sync(0xffffffffu, kt, o);
    float zs = mu + sig * noise[b * 32 + z];
    float zl = linb[z];
    #pragma unroll
    for (int k = 0; k < 32; k++)
        zl += __shfl_sync(0xffffffffu, zs, k) * linW[k * 32 + z];
    float w = softplusf(zl);
    float red = -2.f * w * g_PF[b * 32 + z];
    const float* GG = g_GG + g * 1024;
    float vs = 0.f;
    // GG is symmetric (Hadamard of symmetric Grams): read [k][z] for coalescing
    #pragma unroll
    for (int k = 0; k < 32; k++) vs += GG[k * 32 + z] * __shfl_sync(0xffffffffu, w, k);
    red += w * vs;
    #pragma unroll
    for (int o = 16; o > 0; o >>= 1) red += __shfl_xor_sync(0xffffffffu, red, o);
    float l0 = __shfl_sync(0xffffffffu, zl, 0);
    float l1 = __shfl_sync(0xffffffffu, zl, 1);
    float l2 = __shfl_sync(0xffffffffu, zl, 2);
    if (z == 0) {
        float rec = (g_s2[b] + red) * (1.f / 65536.f);
        l0 += lbias[0]; l1 += lbias[1]; l2 += lbias[2];
        float l3 = 1.f + lbias[3];
        float m = fmaxf(fmaxf(l0, l1), fmaxf(l2, l3));
        float lse = m + logf(expf(l0 - m) + expf(l1 - m) + expf(l2 - m) + expf(l3 - m));
        int lab = labels[b];
        float ll = (lab == 0 ? l0 : lab == 1 ? l1 : lab == 2 ? l2 : l3) - lse;
        g_perb[b] = rec - weights[b] * ll + kt;
    }
}

__global__ void k_final(float* out) {
    __shared__ float red[256];
    int t = threadIdx.x;
    red[t] = g_perb[t] + g_perb[t + 256] + g_perb[t + 512] + g_perb[t + 768];
    __syncthreads();
    for (int o = 128; o > 0; o >>= 1) {
        if (t < o) red[t] += red[t + o];
        __syncthreads();
    }
    if (t == 0) out[0] = red[0] * (1.f / 1024.f) + g_varloss;
}

extern "C" void kernel_launch(void* const* d_in, const int* in_sizes, int n_in,
                              void* d_out, int out_size) {
    const float* feat    = (const float*)d_in[0];
    const int*   labels  = (const int*)d_in[1];
    const int*   groups  = (const int*)d_in[2];
    const float* weights = (const float*)d_in[3];
    const float* noise   = (const float*)d_in[4];
    const float* ge      = (const float*)d_in[5];
    const float* W1      = (const float*)d_in[6];
    const float* b1      = (const float*)d_in[7];
    const float* W2      = (const float*)d_in[8];
    const float* b2      = (const float*)d_in[9];
    const float* ff      = (const float*)d_in[10];
    const float* r1      = (const float*)d_in[11];
    const float* r2      = (const float*)d_in[12];
    const float* linW    = (const float*)d_in[13];
    const float* linb    = (const float*)d_in[14];
    const float* lbias   = (const float*)d_in[15];
    float* out = (float*)d_out;

    cudaFuncSetAttribute(g_mm, cudaFuncAttributeMaxDynamicSharedMemorySize, SM_TOT);

    k_pre<<<1089, 1024>>>(W1, W2, ff, r1, r2, groups);
    g_mm<<<dim3(48, KCS), 128, SM_TOT>>>(feat);
    k_redfac<<<406, 256>>>();
    k_head<<<128, 256>>>(W1, W2, b1, b2, ge, groups, noise, linW, linb,
                         weights, labels, lbias);
    k_final<<<1, 256>>>(out);
}

// round 14
// speedup vs baseline: 1.0864x; 1.0864x over previous
#include <cuda_runtime.h>
#include <cuda_bf16.h>
#include <math.h>

#define BATCH 1024
#define NFEAT 65536
#define ZD 32
#define NG 16
#define NF 64
#define NR 32
#define KCS 16
#define KPC (NFEAT / KCS)     // 4096 K per CTA
#define NSTG (KPC / 64)       // 64 stages of BK=64

typedef unsigned int u32;

__device__ float g_zpart[KCS * BATCH * 96];
__device__ float g_s2part[KCS * BATCH];
__device__ float g_zraw[BATCH * 64];
__device__ float g_PF[BATCH * ZD];
__device__ float g_s2[BATCH];
__device__ float g_spF[NG * ZD * NF];
__device__ float g_spR1[NG * ZD * NR];
__device__ float g_spR2[NG * ZD * NR];
__device__ float g_GG[NG * ZD * ZD];
__device__ float g_perb[BATCH];
__device__ float g_varloss;
__device__ __nv_bfloat16 g_WcT[64 * NFEAT];   // [n][k] bf16 W1|W2 transposed
__device__ int g_sIdx[BATCH];
__device__ int g_gcnt[NG];
__device__ int g_goff[NG];

// dynamic smem layout (bytes)
#define SMO_A    0u           // 2 slots x 64 rows x 72 bf16  (9216 B/slot)
#define SMO_B    18432u       // 2 slots x 96 rows x 72 bf16  (13824 B/slot)
#define SMO_F    46080u       // 2048 floats
#define SMO_R1   54272u       // 1024 floats
#define SMO_R2   58368u       // 1024 floats
#define SMO_IDX  62464u       // 64 ints
#define SM_TOT   62720u

static __device__ __forceinline__ float softplusf(float x) {
    return fmaxf(x, 0.f) + log1pf(expf(-fabsf(x)));
}
static __device__ __forceinline__ u32 cvt2(float a, float b) {
    __nv_bfloat162 h = __floats2bfloat162_rn(a, b);
    return *reinterpret_cast<u32*>(&h);
}
static __device__ __forceinline__ void cpa16(u32 dst, const void* src) {
    asm volatile("cp.async.cg.shared.global [%0], [%1], 16;" :: "r"(dst), "l"(src) : "memory");
}
static __device__ __forceinline__ void sts128(u32 addr, u32 x, u32 y, u32 z, u32 w) {
    asm volatile("st.shared.v4.b32 [%0], {%1,%2,%3,%4};"
                 :: "r"(addr), "r"(x), "r"(y), "r"(z), "r"(w) : "memory");
}
static __device__ __forceinline__ void ldsm4(u32& r0, u32& r1, u32& r2, u32& r3, u32 addr) {
    asm volatile("ldmatrix.sync.aligned.m8n8.x4.shared.b16 {%0,%1,%2,%3}, [%4];"
                 : "=r"(r0), "=r"(r1), "=r"(r2), "=r"(r3) : "r"(addr));
}
static __device__ __forceinline__ void ldsm2(u32& r0, u32& r1, u32 addr) {
    asm volatile("ldmatrix.sync.aligned.m8n8.x2.shared.b16 {%0,%1}, [%2];"
                 : "=r"(r0), "=r"(r1) : "r"(addr));
}
static __device__ __forceinline__ void mma16816(float* c, u32 a0, u32 a1, u32 a2, u32 a3,
                                                u32 b0, u32 b1) {
    asm volatile(
        "mma.sync.aligned.m16n8k16.row.col.f32.bf16.bf16.f32 "
        "{%0,%1,%2,%3}, {%4,%5,%6,%7}, {%8,%9}, {%0,%1,%2,%3};"
        : "+f"(c[0]), "+f"(c[1]), "+f"(c[2]), "+f"(c[3])
        : "r"(a0), "r"(a1), "r"(a2), "r"(a3), "r"(b0), "r"(b1));
}

// ---------------- fused prologue: WcT transpose+cvt | softplus | group sort ------
__global__ void __launch_bounds__(1024) k_pre(const float* __restrict__ W1,
                                              const float* __restrict__ W2,
                                              const float* __restrict__ ff,
                                              const float* __restrict__ r1,
                                              const float* __restrict__ r2,
                                              const int* __restrict__ groups) {
    int bx = blockIdx.x, t = threadIdx.x;
    if (bx < 1024) {
        __shared__ float tile[128][33];
        int w = bx >> 9;
        int k0 = (bx & 511) * 128;
        int tx = t & 31, ty = t >> 5;          // 32 x 32
        const float* W = w ? W2 : W1;
        #pragma unroll
        for (int i = 0; i < 4; i++)
            tile[ty + 32 * i][tx] = W[(size_t)(k0 + ty + 32 * i) * 32 + tx];
        __syncthreads();
        int n = t >> 5;
        int jj = (t & 31) * 2;
        u32* dst = (u32*)(g_WcT + (size_t)(w * 32 + n) * NFEAT + k0);
        #pragma unroll
        for (int q = 0; q < 2; q++) {
            int k = (jj + q) * 2;
            dst[jj + q] = cvt2(tile[k][n], tile[k + 1][n]);
        }
    } else if (bx < 1088) {
        int i = (bx - 1024) * 1024 + t;
        const int nF = NG * ZD * NF, nR = NG * ZD * NR;
        if (i < nF) g_spF[i] = softplusf(ff[i]);
        else if (i < nF + nR) g_spR1[i - nF] = softplusf(r1[i - nF]);
        else if (i < nF + 2 * nR) g_spR2[i - nF - nR] = softplusf(r2[i - nF - nR]);
    } else {
        __shared__ int warpCnt[32][16];
        __shared__ int warpOff[32][16];
        __shared__ int goff[16], gcnt[16];
        int w = t >> 5, lane = t & 31;
        int g = groups[t];
        u32 mOwn = 0;
        #pragma unroll
        for (int gi = 0; gi < 16; gi++) {
            u32 m = __ballot_sync(0xffffffffu, g == gi);
            if (g == gi) mOwn = m;
            if (lane == gi) warpCnt[w][gi] = __popc(m);
        }
        __syncthreads();
        if (t < 16) {
            int s = 0;
            for (int w2 = 0; w2 < 32; w2++) { warpOff[w2][t] = s; s += warpCnt[w2][t]; }
            gcnt[t] = s;
        }
        __syncthreads();
        if (t == 0) {
            int s = 0;
            for (int i = 0; i < 16; i++) { goff[i] = s; s += gcnt[i]; }
        }
        __syncthreads();
        int rank = __popc(mOwn & ((1u << lane) - 1u));
        g_sIdx[goff[g] + warpOff[w][g] + rank] = t;
        if (t < 16) { g_gcnt[t] = gcnt[t]; g_goff[t] = goff[t]; }
    }
}

// ---------------- fused tensor-core GEMM (R12-proven: 64x96, 8 warps, cp.async B) --
__global__ void __launch_bounds__(256) g_mm(const float* __restrict__ feat) {
    extern __shared__ char smc[];
    u32 sbase = (u32)__cvta_generic_to_shared(smc);
    float* sF = (float*)(smc + SMO_F);
    float* sR1 = (float*)(smc + SMO_R1);
    float* sR2 = (float*)(smc + SMO_R2);
    int* sIdx = (int*)(smc + SMO_IDX);

    int mt = blockIdx.x, kc = blockIdx.y;
    int g = mt / 3, ti = mt % 3;
    int nb = g_gcnt[g];
    int m0 = ti * 64;
    if (m0 >= nb) return;
    int p0 = g_goff[g] + m0;
    int vr = nb - m0; if (vr > 64) vr = 64;
    int t = threadIdx.x;

    for (int i = t; i < ZD * NF; i += 256) sF[i] = g_spF[g * ZD * NF + i];
    for (int i = t; i < ZD * NR; i += 256) {
        sR1[i] = g_spR1[g * ZD * NR + i];
        sR2[i] = g_spR2[g * ZD * NR + i];
    }
    if (t < 64) sIdx[t] = g_sIdx[(t < vr) ? (p0 + t) : p0];
    __syncthreads();

    int lane = t & 31, wid = t >> 5;
    int wm = wid & 1, wn = wid >> 1;
    float acc[2][3][4];
    #pragma unroll
    for (int mf = 0; mf < 2; mf++)
        #pragma unroll
        for (int nf = 0; nf < 3; nf++)
            #pragma unroll
            for (int q = 0; q < 4; q++) acc[mf][nf][q] = 0.f;

    int ar = t >> 2, aq = t & 3;
    bool aval = ar < vr;
    const float* arow = feat + (size_t)sIdx[ar] * NFEAT + aq * 16;
    int wz = t >> 3, wi0 = (t & 7) * 8;
    int kb0 = kc * KPC;
    float sq = 0.f;

    int brow = t >> 2, bch = (t & 3) * 2;
    const char* bsrc = (const char*)(g_WcT + (size_t)brow * NFEAT) + bch * 16;
    u32 bdstBase = sbase + SMO_B + (u32)brow * 144 + (u32)bch * 16;

    #define STAGE_B(s, kb)                                                        \
        do {                                                                      \
            u32 _d = bdstBase + ((u32)(s) & 1u) * 13824u;                         \
            const char* _s = bsrc + (size_t)(kb) * 2;                             \
            cpa16(_d, _s); cpa16(_d + 16, _s + 16);                               \
            asm volatile("cp.async.commit_group;");                               \
        } while (0)

    #define STAGE_AWP(s, kb, rg)                                                  \
        do {                                                                      \
            u32 _ab = sbase + SMO_A + ((u32)(s) & 1u) * 9216u + (u32)ar * 144 + (u32)aq * 32; \
            if (aval) {                                                           \
                sq += rg[0].x * rg[0].x + rg[0].y * rg[0].y + rg[0].z * rg[0].z + rg[0].w * rg[0].w; \
                sq += rg[1].x * rg[1].x + rg[1].y * rg[1].y + rg[1].z * rg[1].z + rg[1].w * rg[1].w; \
                sq += rg[2].x * rg[2].x + rg[2].y * rg[2].y + rg[2].z * rg[2].z + rg[2].w * rg[2].w; \
                sq += rg[3].x * rg[3].x + rg[3].y * rg[3].y + rg[3].z * rg[3].z + rg[3].w * rg[3].w; \
            }                                                                     \
            sts128(_ab, cvt2(rg[0].x, rg[0].y), cvt2(rg[0].z, rg[0].w),           \
                        cvt2(rg[1].x, rg[1].y), cvt2(rg[1].z, rg[1].w));          \
            sts128(_ab + 16, cvt2(rg[2].x, rg[2].y), cvt2(rg[2].z, rg[2].w),      \
                             cvt2(rg[3].x, rg[3].y), cvt2(rg[3].z, rg[3].w));     \
            int _f = (kb) >> 10, _r0 = ((kb) >> 5) & 31;                          \
            float _c0 = sF[wz * NF + _f] * sR1[wz * NR + _r0 + (wi0 >> 5)];       \
            int _s0 = wi0 & 31;                                                   \
            sts128(sbase + SMO_B + ((u32)(s) & 1u) * 13824u + (u32)(64 + wz) * 144 + (u32)wi0 * 2, \
                   cvt2(_c0 * sR2[wz * NR + _s0 + 0], _c0 * sR2[wz * NR + _s0 + 1]), \
                   cvt2(_c0 * sR2[wz * NR + _s0 + 2], _c0 * sR2[wz * NR + _s0 + 3]), \
                   cvt2(_c0 * sR2[wz * NR + _s0 + 4], _c0 * sR2[wz * NR + _s0 + 5]), \
                   cvt2(_c0 * sR2[wz * NR + _s0 + 6], _c0 * sR2[wz * NR + _s0 + 7])); \
        } while (0)

    float4 rNext[4], rFar[4];
    STAGE_B(0, kb0);
    STAGE_B(1, kb0 + 64);
    {
        float4 rNow[4] = {};
        if (aval) {
            const float4* s4 = (const float4*)(arow + kb0);
            #pragma unroll
            for (int i = 0; i < 4; i++) rNow[i] = s4[i];
            const float4* s5 = (const float4*)(arow + kb0 + 64);
            #pragma unroll
            for (int i = 0; i < 4; i++) rNext[i] = s5[i];
        }
        STAGE_AWP(0, kb0, rNow);
    }

    for (int kt = 0; kt < NSTG; kt++) {
        asm volatile("cp.async.wait_group 1;");
        __syncthreads();
        if (aval && kt + 2 < NSTG) {
            const float4* s4 = (const float4*)(arow + kb0 + (kt + 2) * 64);
            #pragma unroll
            for (int i = 0; i < 4; i++) rFar[i] = s4[i];
        }
        {
            u32 aBase = sbase + SMO_A + ((u32)kt & 1u) * 9216u;
            u32 bBase = sbase + SMO_B + ((u32)kt & 1u) * 13824u;
            #pragma unroll
            for (int ks = 0; ks < 4; ks++) {
                int kbs = ks * 16;
                u32 b0[3], b1[3];
                #pragma unroll
                for (int nf = 0; nf < 3; nf++) {
                    int n = wn * 24 + nf * 8 + (lane & 7);
                    ldsm2(b0[nf], b1[nf], bBase + (u32)(n * 72 + kbs + ((lane >> 3) & 1) * 8) * 2);
                }
                #pragma unroll
                for (int mf = 0; mf < 2; mf++) {
                    int row = wm * 32 + mf * 16 + (lane & 15);
                    u32 a0, a1, a2, a3;
                    ldsm4(a0, a1, a2, a3, aBase + (u32)(row * 72 + kbs + (lane >> 4) * 8) * 2);
                    #pragma unroll
                    for (int nf = 0; nf < 3; nf++)
                        mma16816(acc[mf][nf], a0, a1, a2, a3, b0[nf], b1[nf]);
                }
            }
        }
        __syncthreads();
        if (kt + 1 < NSTG) {
            STAGE_AWP(kt + 1, kb0 + (kt + 1) * 64, rNext);
            if (kt + 2 < NSTG) {
                STAGE_B(kt + 2, kb0 + (kt + 2) * 64);
            } else {
                asm volatile("cp.async.commit_group;");
            }
            #pragma unroll
            for (int i = 0; i < 4; i++) rNext[i] = rFar[i];
        } else {
            asm volatile("cp.async.commit_group;");
        }
    }

    sq += __shfl_down_sync(0xffffffffu, sq, 2, 4);
    sq += __shfl_down_sync(0xffffffffu, sq, 1, 4);
    if (aq == 0 && aval) g_s2part[kc * BATCH + p0 + ar] = sq;

    #pragma unroll
    for (int mf = 0; mf < 2; mf++) {
        #pragma unroll
        for (int half = 0; half < 2; half++) {
            int r = wm * 32 + mf * 16 + (lane >> 2) + half * 8;
            if (r < vr) {
                int p = p0 + r;
                float* dst = g_zpart + ((size_t)kc * BATCH + p) * 96;
                #pragma unroll
                for (int nf = 0; nf < 3; nf++) {
                    int ncol = wn * 24 + nf * 8 + (lane & 3) * 2;
                    float2 v = half ? make_float2(acc[mf][nf][2], acc[mf][nf][3])
                                    : make_float2(acc[mf][nf][0], acc[mf][nf][1]);
                    *(float2*)(dst + ncol) = v;
                }
            }
        }
    }
    #undef STAGE_B
    #undef STAGE_AWP
}

// ---------------- fused: reduce split-K partials | gram | varloss ----------------
__global__ void k_redfac() {
    int bx = blockIdx.x, t = threadIdx.x;
    if (bx < 389) {
        int i = bx * 256 + t;
        if (i < BATCH * 96) {
            int p = i / 96, n = i - p * 96;
            float s = 0.f;
            for (int kc = 0; kc < KCS; kc++) s += g_zpart[((size_t)kc * BATCH + p) * 96 + n];
            int b = g_sIdx[p];
            if (n < 64) g_zraw[b * 64 + n] = s;
            else g_PF[b * 32 + n - 64] = s;
        } else if (i < BATCH * 96 + BATCH) {
            int p = i - BATCH * 96;
            float s = 0.f;
            for (int kc = 0; kc < KCS; kc++) s += g_s2part[kc * BATCH + p];
            g_s2[g_sIdx[p]] = s;
        }
    } else if (bx < 405) {
        __shared__ float s1[ZD * NR], s2m[ZD * NR], sf[ZD * NF];
        int g = bx - 389;
        for (int i = t; i < ZD * NR; i += 256) {
            s1[i] = g_spR1[g * ZD * NR + i];
            s2m[i] = g_spR2[g * ZD * NR + i];
        }
        for (int i = t; i < ZD * NF; i += 256) sf[i] = g_spF[g * ZD * NF + i];
        __syncthreads();
        for (int q = t; q < ZD * ZD; q += 256) {
            int z = q >> 5, z2 = q & 31;
            float a = 0.f, b = 0.f, c = 0.f;
            #pragma unroll
            for (int r = 0; r < NR; r++) {
                a += s1[z * NR + r] * s1[z2 * NR + r];
                b += s2m[z * NR + r] * s2m[z2 * NR + r];
            }
            #pragma unroll
            for (int f = 0; f < NF; f++) c += sf[z * NF + f] * sf[z2 * NF + f];
            g_GG[g * ZD * ZD + q] = a * b * c;
        }
    } else {
        __shared__ float rf[256], rr[256];
        float af = 0.f, ar = 0.f;
        for (int idx = t; idx < 4096; idx += 256) {
            float s = 0.f, ss = 0.f;
            if (idx < 2048) {
                #pragma unroll
                for (int g = 0; g < 16; g++) { float x = g_spF[g * 2048 + idx]; s += x; ss += x * x; }
                af += (ss - s * s * (1.f / 16.f)) * (1.f / 15.f);
            } else if (idx < 3072) {
                int j = idx - 2048;
                #pragma unroll
                for (int g = 0; g < 16; g++) { float x = g_spR1[g * 1024 + j]; s += x; ss += x * x; }
                ar += (ss - s * s * (1.f / 16.f)) * (1.f / 15.f);
            } else {
                int j = idx - 3072;
                #pragma unroll
                for (int g = 0; g < 16; g++) { float x = g_spR2[g * 1024 + j]; s += x; ss += x * x; }
                ar += (ss - s * s * (1.f / 16.f)) * (1.f / 15.f);
            }
        }
        rf[t] = af; rr[t] = ar;
        __syncthreads();
        for (int o = 128; o > 0; o >>= 1) {
            if (t < o) { rf[t] += rf[t + o]; rr[t] += rr[t + o]; }
            __syncthreads();
        }
        if (t == 0) g_varloss = rf[0] * (1.f / 64.f) + rr[0] * (1.f / 32.f);
    }
}

// ---------------- fused VAE head + per-sample assembly ----------------
__global__ void k_head(const float* __restrict__ W1, const float* __restrict__ W2,
                       const float* __restrict__ b1, const float* __restrict__ b2,
                       const float* __restrict__ ge, const int* __restrict__ groups,
                       const float* __restrict__ noise, const float* __restrict__ linW,
                       const float* __restrict__ linb, const float* __restrict__ weights,
                       const int* __restrict__ labels, const float* __restrict__ lbias) {
    int t = threadIdx.x, b = blockIdx.x * 8 + (t >> 5), z = t & 31;
    int g = groups[b];
    float e0 = ge[g * 2], e1 = ge[g * 2 + 1];
    float mu = g_zraw[b * 64 + z] + b1[z] + e0 * W1[65536 * 32 + z] + e1 * W1[65537 * 32 + z];
    float ls = g_zraw[b * 64 + 32 + z] + b2[z] + e0 * W2[65536 * 32 + z] + e1 * W2[65537 * 32 + z];
    float sig = 1e-6f + expf(ls);
    float kt = -logf(sig) + 0.5f * (sig * sig + mu * mu - 1.f);
    #pragma unroll
    for (int o = 16; o > 0; o >>= 1) kt += __shfl_xor_sync(0xffffffffu, kt, o);
    float zs = mu + sig * noise[b * 32 + z];
    float zl = linb[z];
    #pragma unroll
    for (int k = 0; k < 32; k++)
        zl += __shfl_sync(0xffffffffu, zs, k) * linW[k * 32 + z];
    float w = softplusf(zl);
    float red = -2.f * w * g_PF[b * 32 + z];
    const float* GG = g_GG + g * 1024;
    float vs = 0.f;
    // GG is symmetric (Hadamard of symmetric Grams): read [k][z] for coalescing
    #pragma unroll
    for (int k = 0; k < 32; k++) vs += GG[k * 32 + z] * __shfl_sync(0xffffffffu, w, k);
    red += w * vs;
    #pragma unroll
    for (int o = 16; o > 0; o >>= 1) red += __shfl_xor_sync(0xffffffffu, red, o);
    float l0 = __shfl_sync(0xffffffffu, zl, 0);
    float l1 = __shfl_sync(0xffffffffu, zl, 1);
    float l2 = __shfl_sync(0xffffffffu, zl, 2);
    if (z == 0) {
        float rec = (g_s2[b] + red) * (1.f / 65536.f);
        l0 += lbias[0]; l1 += lbias[1]; l2 += lbias[2];
        float l3 = 1.f + lbias[3];
        float m = fmaxf(fmaxf(l0, l1), fmaxf(l2, l3));
        float lse = m + logf(expf(l0 - m) + expf(l1 - m) + expf(l2 - m) + expf(l3 - m));
        int lab = labels[b];
        float ll = (lab == 0 ? l0 : lab == 1 ? l1 : lab == 2 ? l2 : l3) - lse;
        g_perb[b] = rec - weights[b] * ll + kt;
    }
}

__global__ void k_final(float* out) {
    __shared__ float red[256];
    int t = threadIdx.x;
    red[t] = g_perb[t] + g_perb[t + 256] + g_perb[t + 512] + g_perb[t + 768];
    __syncthreads();
    for (int o = 128; o > 0; o >>= 1) {
        if (t < o) red[t] += red[t + o];
        __syncthreads();
    }
    if (t == 0) out[0] = red[0] * (1.f / 1024.f) + g_varloss;
}

extern "C" void kernel_launch(void* const* d_in, const int* in_sizes, int n_in,
                              void* d_out, int out_size) {
    const float* feat    = (const float*)d_in[0];
    const int*   labels  = (const int*)d_in[1];
    const int*   groups  = (const int*)d_in[2];
    const float* weights = (const float*)d_in[3];
    const float* noise   = (const float*)d_in[4];
    const float* ge      = (const float*)d_in[5];
    const float* W1      = (const float*)d_in[6];
    const float* b1      = (const float*)d_in[7];
    const float* W2      = (const float*)d_in[8];
    const float* b2      = (const float*)d_in[9];
    const float* ff      = (const float*)d_in[10];
    const float* r1      = (const float*)d_in[11];
    const float* r2      = (const float*)d_in[12];
    const float* linW    = (const float*)d_in[13];
    const float* linb    = (const float*)d_in[14];
    const float* lbias   = (const float*)d_in[15];
    float* out = (float*)d_out;

    cudaFuncSetAttribute(g_mm, cudaFuncAttributeMaxDynamicSharedMemorySize, SM_TOT);

    k_pre<<<1089, 1024>>>(W1, W2, ff, r1, r2, groups);
    g_mm<<<dim3(48, KCS), 256, SM_TOT>>>(feat);
    k_redfac<<<406, 256>>>();
    k_head<<<128, 256>>>(W1, W2, b1, b2, ge, groups, noise, linW, linb,
                         weights, labels, lbias);
    k_final<<<1, 256>>>(out);
}